// round 16
// baseline (speedup 1.0000x reference)
#include <cuda_runtime.h>
#include <cuda_bf16.h>
#include <math.h>
#include <stdint.h>

// ---------------- constants ----------------
#define BATCH   8
#define SEQ     512
#define HID     768
#define NHEADS  12
#define HDIM    64
#define FFDIM   3072
#define NLAYERS 12
#define ROWS    (BATCH*SEQ)          // 4096
#define NBH     (BATCH*NHEADS)       // 96

typedef __nv_bfloat16 bf;

// ---------------- scratch (device globals; allocation-free) ----------------
__device__ float g_hidden[ROWS*HID];
__device__ float g_tmp   [ROWS*HID];
__device__ float g_pb    [NHEADS*SEQ*SEQ];
__device__ float g_mask  [ROWS];

__device__ bf g_hidA_hi[ROWS*HID], g_hidA_lo[ROWS*HID];
__device__ bf g_q_hi [ROWS*HID], g_q_lo [ROWS*HID];   // [B,H,S,64]
__device__ bf g_k_hi [ROWS*HID], g_k_lo [ROWS*HID];   // [B,H,S,64]
__device__ bf g_vt_hi[ROWS*HID], g_vt_lo[ROWS*HID];   // [B,H,64,S]
__device__ bf g_ctx_hi[ROWS*HID], g_ctx_lo[ROWS*HID]; // [B*S,768]
__device__ bf g_ff_hi[ROWS*FFDIM], g_ff_lo[ROWS*FFDIM];

__device__ bf g_WqkvT_hi[3*HID*HID], g_WqkvT_lo[3*HID*HID];  // [2304,768]
__device__ bf g_WoT_hi[HID*HID],  g_WoT_lo[HID*HID];
__device__ bf g_W1T_hi[HID*FFDIM], g_W1T_lo[HID*FFDIM]; // [3072,768]
__device__ bf g_W2T_hi[HID*FFDIM], g_W2T_lo[HID*FFDIM]; // [768,3072]

// ---------------- PTX helpers (sm_100 baseline only) ----------------
__device__ __forceinline__ uint32_t smem_u32(const void* p){
    uint32_t a;
    asm("{ .reg .u64 t; cvta.to.shared.u64 t, %1; cvt.u32.u64 %0, t; }" : "=r"(a) : "l"(p));
    return a;
}
__device__ __forceinline__ void cp16(uint32_t dst, const void* src){
    asm volatile("cp.async.cg.shared.global [%0], [%1], 16;" :: "r"(dst), "l"(src));
}
#define CP_COMMIT() asm volatile("cp.async.commit_group;" ::: "memory")
#define CP_WAIT(n)  asm volatile("cp.async.wait_group %0;" :: "n"(n) : "memory")

__device__ __forceinline__ void ldsm4(uint32_t* r, uint32_t addr){
    asm volatile("ldmatrix.sync.aligned.m8n8.x4.shared.b16 {%0,%1,%2,%3}, [%4];"
                 : "=r"(r[0]), "=r"(r[1]), "=r"(r[2]), "=r"(r[3]) : "r"(addr));
}

__device__ __forceinline__ void mma16816(float* d, const uint32_t* a,
                                         uint32_t b0, uint32_t b1){
    asm volatile(
        "mma.sync.aligned.m16n8k16.row.col.f32.bf16.bf16.f32 "
        "{%0,%1,%2,%3}, {%4,%5,%6,%7}, {%8,%9}, {%0,%1,%2,%3};"
        : "+f"(d[0]), "+f"(d[1]), "+f"(d[2]), "+f"(d[3])
        : "r"(a[0]), "r"(a[1]), "r"(a[2]), "r"(a[3]), "r"(b0), "r"(b1));
}

__device__ __forceinline__ void bsplit(float v, bf& h, bf& l){
    h = __float2bfloat16(v);
    l = __float2bfloat16(v - __bfloat162float(h));
}

// ---------------- reductions ----------------
__device__ __forceinline__ float warpSum(float v){
#pragma unroll
    for (int o=16;o>0;o>>=1) v += __shfl_xor_sync(0xffffffffu, v, o);
    return v;
}
__device__ float blockSum(float v){
    __shared__ float sh[8];
    __shared__ float total;
    int lane = threadIdx.x & 31, wid = threadIdx.x >> 5;
    v = warpSum(v);
    __syncthreads();
    if (lane == 0) sh[wid] = v;
    __syncthreads();
    if (wid == 0){
        float r = (lane < 8) ? sh[lane] : 0.f;
        r = warpSum(r);
        if (lane == 0) total = r;
    }
    __syncthreads();
    return total;
}

// ---------------- small kernels ----------------
__global__ void split_copy_k(const float* __restrict__ src, float* __restrict__ dstF,
                             bf* __restrict__ hi, bf* __restrict__ lo, int n){
    int i = blockIdx.x*blockDim.x + threadIdx.x;
    if (i >= n) return;
    float v = src[i];
    dstF[i] = v;
    bf h, l; bsplit(v, h, l);
    hi[i] = h; lo[i] = l;
}

__global__ void mask_k(const int* __restrict__ seg, float* __restrict__ mask){
    int i = blockIdx.x*blockDim.x + threadIdx.x;
    if (i < ROWS) mask[i] = (seg[i] > 0) ? 0.f : -10000.f;
}

__device__ __forceinline__ int rel_bucket(int qpos, int kpos){
    int rel = kpos - qpos;
    int off = (rel > 0) ? 16 : 0;
    int ar  = rel < 0 ? -rel : rel;
    if (ar < 8) return off + ar;
    float t = logf((float)ar / 8.0f) / 2.772588722239781f * 8.0f;
    int v = 8 + (int)t;
    if (v > 15) v = 15;
    return off + v;
}

__global__ void posbias_k(const float* __restrict__ rel_emb, float* __restrict__ pb){
    int idx = blockIdx.x*blockDim.x + threadIdx.x;
    if (idx >= SEQ*SEQ) return;
    int q = idx >> 9, k = idx & 511;
    int bkt = rel_bucket(q, k);
#pragma unroll
    for (int h=0; h<NHEADS; h++)
        pb[((long)h*SEQ + q)*SEQ + k] = rel_emb[bkt*NHEADS + h];
}

// W[K,N] fp32 -> WT hi/lo [N,K] bf16
__global__ void tsplit_k(const float* __restrict__ W,
                         bf* __restrict__ Thi, bf* __restrict__ Tlo,
                         int K, int N){
    __shared__ float t[32][33];
    int k0 = blockIdx.y*32, n0 = blockIdx.x*32;
    int x = threadIdx.x, y = threadIdx.y;
#pragma unroll
    for (int i=y; i<32; i+=8) t[i][x] = W[(long)(k0+i)*N + n0 + x];
    __syncthreads();
#pragma unroll
    for (int i=y; i<32; i+=8){
        float v = t[x][i];
        bf h, l; bsplit(v, h, l);
        long o = (long)(n0+i)*K + k0 + x;
        Thi[o] = h; Tlo[o] = l;
    }
}

// fused QKV-weight transpose-split: grid.z selects Wq/Wk/Wv
__global__ void tsplit_qkv_k(const float* __restrict__ Wq, const float* __restrict__ Wk,
                             const float* __restrict__ Wv,
                             bf* __restrict__ Thi, bf* __restrict__ Tlo){
    __shared__ float t[32][33];
    const float* W = (blockIdx.z==0) ? Wq : (blockIdx.z==1) ? Wk : Wv;
    bf* Th = Thi + (long)blockIdx.z*HID*HID;
    bf* Tl = Tlo + (long)blockIdx.z*HID*HID;
    int k0 = blockIdx.y*32, n0 = blockIdx.x*32;
    int x = threadIdx.x, y = threadIdx.y;
#pragma unroll
    for (int i=y; i<32; i+=8) t[i][x] = W[(long)(k0+i)*HID + n0 + x];
    __syncthreads();
#pragma unroll
    for (int i=y; i<32; i+=8){
        float v = t[x][i];
        bf h, l; bsplit(v, h, l);
        long o = (long)(n0+i)*HID + k0 + x;
        Th[o] = h; Tl[o] = l;
    }
}

__global__ __launch_bounds__(256) void resln_k(
    const float* __restrict__ resid, const float* __restrict__ x,
    const float* __restrict__ g, const float* __restrict__ b,
    float* __restrict__ out,
    bf* __restrict__ ohi, bf* __restrict__ olo)
{
    long base = (long)blockIdx.x * HID;
    int t = threadIdx.x;
    float v[3]; float s = 0.f;
#pragma unroll
    for (int i=0;i<3;i++){ v[i] = resid[base + t + 256*i] + x[base + t + 256*i]; s += v[i]; }
    s = blockSum(s);
    float mean = s * (1.f/768.f);
    float q = 0.f;
#pragma unroll
    for (int i=0;i<3;i++){ float d = v[i]-mean; q += d*d; }
    q = blockSum(q);
    float inv = 1.f / sqrtf(q*(1.f/768.f) + 1e-6f);
#pragma unroll
    for (int i=0;i<3;i++){
        int c = t + 256*i;
        float r = g[c]*(v[i]-mean)*inv + b[c];
        out[base + c] = r;
        bf h, l; bsplit(r, h, l);
        ohi[base + c] = h; olo[base + c] = l;
    }
}

// ---------------- fused flash attention ----------------
#define FLASH_SMEM 168192   // 167936 + 256 alignment pad

__global__ __launch_bounds__(512,1) void flash_k(
    const bf* __restrict__ Qh, const bf* __restrict__ Ql,
    const bf* __restrict__ Kh, const bf* __restrict__ Kl,
    const bf* __restrict__ Vth, const bf* __restrict__ Vtl,
    const float* __restrict__ pbias, const float* __restrict__ mk,
    bf* __restrict__ ctxHi, bf* __restrict__ ctxLo)
{
    constexpr int Q_HI=0, Q_LO=16384, K_HI=32768, K_LO=49152;
    constexpr int V_HI=65536, V_LO=81920, P_HI=98304, P_LO=131072;
    constexpr int REDM=163840, REDS=165888;
    extern __shared__ __align__(16) char smem0[];
    const uint32_t sb0 = smem_u32(smem0);
    const uint32_t sb  = (sb0 + 255u) & ~255u;      // 256-aligned base
    char* smem = smem0 + (sb - sb0);
    float* redM = (float*)(smem + REDM);
    float* redS = (float*)(smem + REDS);

    const int tid=threadIdx.x, lane=tid&31, warp=tid>>5;
    const int warpM = warp>>2, warpN = warp&3;
    const int q0 = blockIdx.x*128, bh = blockIdx.y;
    const int b = bh/NHEADS, h = bh - b*NHEADS;
    const long baseQK = (long)bh*SEQ*HDIM;
    const long baseV  = (long)bh*HDIM*SEQ;

    const int lt = lane>>3, lrow = ((lt&1)<<3)+(lane&7), lcol = (lt>>1)<<4;
    const int qr = lane>>2, qc = (lane&3)*2;

    // precomputed ldsm base addresses (kk=0); addr(kk) = base ^ (kk<<5)
    uint32_t aQh[2], aQl[2], aKh[2], aKl[2], aPh[2], aPl[2], aVh, aVl;
#pragma unroll
    for (int mt=0;mt<2;mt++){
        int r = warpM*32 + mt*16 + lrow;
        uint32_t sw = (uint32_t)(lcol ^ ((r&7)<<4));
        aQh[mt] = sb + Q_HI + r*128 + sw;
        aQl[mt] = sb + Q_LO + r*128 + sw;
        aPh[mt] = sb + P_HI + r*256 + sw;
        aPl[mt] = sb + P_LO + r*256 + sw;
    }
#pragma unroll
    for (int g=0;g<2;g++){
        int r = warpN*32 + g*16 + lrow;
        uint32_t sw = (uint32_t)(lcol ^ ((r&7)<<4));
        aKh[g] = sb + K_HI + r*128 + sw;
        aKl[g] = sb + K_LO + r*128 + sw;
    }
    {
        int n = warpN*16 + lrow;
        uint32_t sw = (uint32_t)(lcol ^ ((n&7)<<4));
        aVh = sb + V_HI + n*256 + sw;
        aVl = sb + V_LO + n*256 + sw;
    }

    // Q load (once) — branch-free, strength-reduced
    {
        const int rk = tid>>3, ck = tid&7;
        const uint32_t dsw = (uint32_t)(rk*128) + (uint32_t)((ck*16)^((rk&7)<<4));
        const bf* sQh = Qh + baseQK + (long)(q0+rk)*HDIM + ck*8;
        const bf* sQl = Ql + baseQK + (long)(q0+rk)*HDIM + ck*8;
        uint32_t d = sb + Q_HI + dsw;
#pragma unroll
        for (int k=0;k<2;k++){ cp16(d, sQh); sQh += 64*HDIM; d += 64*128; }
        d = sb + Q_LO + dsw;
#pragma unroll
        for (int k=0;k<2;k++){ cp16(d, sQl); sQl += 64*HDIM; d += 64*128; }
    }
    auto loadKV = [&](int j){
        const int rk = tid>>3, ck = tid&7;
        const uint32_t dswk = (uint32_t)(rk*128) + (uint32_t)((ck*16)^((rk&7)<<4));
        const bf* sKh = Kh + baseQK + (long)(j*128+rk)*HDIM + ck*8;
        const bf* sKl = Kl + baseQK + (long)(j*128+rk)*HDIM + ck*8;
        uint32_t d = sb + K_HI + dswk;
#pragma unroll
        for (int k=0;k<2;k++){ cp16(d, sKh); sKh += 64*HDIM; d += 64*128; }
        d = sb + K_LO + dswk;
#pragma unroll
        for (int k=0;k<2;k++){ cp16(d, sKl); sKl += 64*HDIM; d += 64*128; }
        const int rv = tid>>4, cv = tid&15;
        const uint32_t dswv = (uint32_t)(rv*256) + (uint32_t)((cv*16)^((rv&7)<<4));
        const bf* sVh = Vth + baseV + (long)rv*SEQ + j*128 + cv*8;
        const bf* sVl = Vtl + baseV + (long)rv*SEQ + j*128 + cv*8;
        d = sb + V_HI + dswv;
#pragma unroll
        for (int k=0;k<2;k++){ cp16(d, sVh); sVh += 32*SEQ; d += 32*256; }
        d = sb + V_LO + dswv;
#pragma unroll
        for (int k=0;k<2;k++){ cp16(d, sVl); sVl += 32*SEQ; d += 32*256; }
        CP_COMMIT();
    };
    loadKV(0);

    float m_run[4], l_run[4];
#pragma unroll
    for (int i=0;i<4;i++){ m_run[i] = -3.0e38f; l_run[i] = 0.f; }
    float oacc[2][2][4];
#pragma unroll
    for (int mt=0;mt<2;mt++)
#pragma unroll
        for (int nt=0;nt<2;nt++)
#pragma unroll
            for (int e=0;e<4;e++) oacc[mt][nt][e] = 0.f;

    for (int j=0;j<4;j++){
        CP_WAIT(0); __syncthreads();

        float acc[2][4][4];
#pragma unroll
        for (int mt=0;mt<2;mt++)
#pragma unroll
            for (int nt=0;nt<4;nt++)
#pragma unroll
                for (int e=0;e<4;e++) acc[mt][nt][e] = 0.f;
#pragma unroll
        for (int kk=0;kk<4;kk++){
            const uint32_t kb = (uint32_t)(kk<<5);
            uint32_t ah[2][4], al[2][4];
#pragma unroll
            for (int mt=0;mt<2;mt++){
                ldsm4(ah[mt], aQh[mt] ^ kb);
                ldsm4(al[mt], aQl[mt] ^ kb);
            }
            uint32_t bhf[2][4], blf[2][4];
#pragma unroll
            for (int g=0; g<2; g++){
                ldsm4(bhf[g], aKh[g] ^ kb);
                ldsm4(blf[g], aKl[g] ^ kb);
            }
#pragma unroll
            for (int mt=0;mt<2;mt++)
#pragma unroll
                for (int nt=0;nt<4;nt++)
                    mma16816(acc[mt][nt], ah[mt], bhf[nt>>1][nt&1], bhf[nt>>1][(nt&1)+2]);
#pragma unroll
            for (int mt=0;mt<2;mt++)
#pragma unroll
                for (int nt=0;nt<4;nt++)
                    mma16816(acc[mt][nt], ah[mt], blf[nt>>1][nt&1], blf[nt>>1][(nt&1)+2]);
#pragma unroll
            for (int mt=0;mt<2;mt++)
#pragma unroll
                for (int nt=0;nt<4;nt++)
                    mma16816(acc[mt][nt], al[mt], bhf[nt>>1][nt&1], bhf[nt>>1][(nt&1)+2]);
        }

        float pmax[4] = {-3.0e38f,-3.0e38f,-3.0e38f,-3.0e38f};
#pragma unroll
        for (int mt=0;mt<2;mt++){
            int r0 = q0 + warpM*32 + mt*16 + qr;
            const float* pbr0 = pbias + ((long)h*SEQ + r0)*SEQ;
            const float* pbr1 = pbr0 + 8*SEQ;
#pragma unroll
            for (int nt=0;nt<4;nt++){
                int col = j*128 + warpN*32 + nt*8 + qc;
                float2 p0 = *(const float2*)(pbr0 + col);
                float2 p1 = *(const float2*)(pbr1 + col);
                float2 mv = *(const float2*)(mk + b*SEQ + col);
                acc[mt][nt][0] = acc[mt][nt][0]*0.125f + p0.x + mv.x;
                acc[mt][nt][1] = acc[mt][nt][1]*0.125f + p0.y + mv.y;
                acc[mt][nt][2] = acc[mt][nt][2]*0.125f + p1.x + mv.x;
                acc[mt][nt][3] = acc[mt][nt][3]*0.125f + p1.y + mv.y;
                pmax[mt*2]   = fmaxf(pmax[mt*2],   fmaxf(acc[mt][nt][0], acc[mt][nt][1]));
                pmax[mt*2+1] = fmaxf(pmax[mt*2+1], fmaxf(acc[mt][nt][2], acc[mt][nt][3]));
            }
        }
#pragma unroll
        for (int ri=0;ri<4;ri++){
            pmax[ri] = fmaxf(pmax[ri], __shfl_xor_sync(0xffffffffu, pmax[ri], 1));
            pmax[ri] = fmaxf(pmax[ri], __shfl_xor_sync(0xffffffffu, pmax[ri], 2));
        }
        if ((lane&3)==0){
#pragma unroll
            for (int ri=0;ri<4;ri++){
                int rl = warpM*32 + (ri>>1)*16 + qr + (ri&1)*8;
                redM[rl*4 + warpN] = pmax[ri];
            }
        }
        __syncthreads();

        float alpha[4];
#pragma unroll
        for (int ri=0;ri<4;ri++){
            int rl = warpM*32 + (ri>>1)*16 + qr + (ri&1)*8;
            float tm = fmaxf(fmaxf(redM[rl*4],redM[rl*4+1]), fmaxf(redM[rl*4+2],redM[rl*4+3]));
            float mn = fmaxf(m_run[ri], tm);
            alpha[ri] = expf(m_run[ri] - mn);
            m_run[ri] = mn;
        }

        float psum[4] = {0.f,0.f,0.f,0.f};
#pragma unroll
        for (int mt=0;mt<2;mt++){
            int rl0 = warpM*32 + mt*16 + qr;
            int rl1 = rl0 + 8;
#pragma unroll
            for (int nt=0;nt<4;nt++){
                float e0 = expf(acc[mt][nt][0] - m_run[mt*2]);
                float e1 = expf(acc[mt][nt][1] - m_run[mt*2]);
                float e2 = expf(acc[mt][nt][2] - m_run[mt*2+1]);
                float e3 = expf(acc[mt][nt][3] - m_run[mt*2+1]);
                psum[mt*2]   += e0 + e1;
                psum[mt*2+1] += e2 + e3;
                int colb = (warpN*32 + nt*8 + qc)*2;
                bf h0,l0,h1,l1,h2,l2,h3,l3;
                bsplit(e0,h0,l0); bsplit(e1,h1,l1);
                bsplit(e2,h2,l2); bsplit(e3,h3,l3);
                uint32_t sw0 = (uint32_t)colb ^ ((uint32_t)(rl0&7)<<4);
                uint32_t sw1 = (uint32_t)colb ^ ((uint32_t)(rl1&7)<<4);
                *(__nv_bfloat162*)(smem + P_HI + rl0*256 + sw0) = __nv_bfloat162(h0,h1);
                *(__nv_bfloat162*)(smem + P_LO + rl0*256 + sw0) = __nv_bfloat162(l0,l1);
                *(__nv_bfloat162*)(smem + P_HI + rl1*256 + sw1) = __nv_bfloat162(h2,h3);
                *(__nv_bfloat162*)(smem + P_LO + rl1*256 + sw1) = __nv_bfloat162(l2,l3);
            }
        }
#pragma unroll
        for (int ri=0;ri<4;ri++){
            psum[ri] += __shfl_xor_sync(0xffffffffu, psum[ri], 1);
            psum[ri] += __shfl_xor_sync(0xffffffffu, psum[ri], 2);
        }
        if ((lane&3)==0){
#pragma unroll
            for (int ri=0;ri<4;ri++){
                int rl = warpM*32 + (ri>>1)*16 + qr + (ri&1)*8;
                redS[rl*4 + warpN] = psum[ri];
            }
        }
        __syncthreads();

#pragma unroll
        for (int ri=0;ri<4;ri++){
            int rl = warpM*32 + (ri>>1)*16 + qr + (ri&1)*8;
            float ts = redS[rl*4] + redS[rl*4+1] + redS[rl*4+2] + redS[rl*4+3];
            l_run[ri] = alpha[ri]*l_run[ri] + ts;
        }
#pragma unroll
        for (int mt=0;mt<2;mt++)
#pragma unroll
            for (int nt=0;nt<2;nt++)
#pragma unroll
                for (int e=0;e<4;e++) oacc[mt][nt][e] *= alpha[mt*2 + (e>>1)];

#pragma unroll
        for (int ks=0;ks<8;ks++){
            const uint32_t kb2 = (uint32_t)(ks<<5);
            uint32_t pah[2][4], pal[2][4];
#pragma unroll
            for (int mt=0;mt<2;mt++){
                ldsm4(pah[mt], aPh[mt] ^ kb2);
                ldsm4(pal[mt], aPl[mt] ^ kb2);
            }
            uint32_t vbh[4], vbl[4];
            ldsm4(vbh, aVh ^ kb2);
            ldsm4(vbl, aVl ^ kb2);
#pragma unroll
            for (int mt=0;mt<2;mt++)
#pragma unroll
                for (int nt=0;nt<2;nt++)
                    mma16816(oacc[mt][nt], pah[mt], vbh[nt], vbh[nt+2]);
#pragma unroll
            for (int mt=0;mt<2;mt++)
#pragma unroll
                for (int nt=0;nt<2;nt++)
                    mma16816(oacc[mt][nt], pah[mt], vbl[nt], vbl[nt+2]);
#pragma unroll
            for (int mt=0;mt<2;mt++)
#pragma unroll
                for (int nt=0;nt<2;nt++)
                    mma16816(oacc[mt][nt], pal[mt], vbh[nt], vbh[nt+2]);
        }
        __syncthreads();
        if (j < 3) loadKV(j+1);
    }

    float inv[4];
#pragma unroll
    for (int ri=0;ri<4;ri++) inv[ri] = 1.f / l_run[ri];
#pragma unroll
    for (int mt=0;mt<2;mt++){
        int m0 = q0 + warpM*32 + mt*16 + qr;
#pragma unroll
        for (int nt=0;nt<2;nt++){
            int col = h*HDIM + warpN*16 + nt*8 + qc;
            long i0 = ((long)(b*SEQ + m0))*HID + col;
            long i1 = i0 + 8L*HID;
            float e0 = oacc[mt][nt][0]*inv[mt*2];
            float e1 = oacc[mt][nt][1]*inv[mt*2];
            float e2 = oacc[mt][nt][2]*inv[mt*2+1];
            float e3 = oacc[mt][nt][3]*inv[mt*2+1];
            bf h0,l0,h1,l1,h2,l2,h3,l3;
            bsplit(e0,h0,l0); bsplit(e1,h1,l1);
            bsplit(e2,h2,l2); bsplit(e3,h3,l3);
            *(__nv_bfloat162*)&ctxHi[i0] = __nv_bfloat162(h0,h1);
            *(__nv_bfloat162*)&ctxLo[i0] = __nv_bfloat162(l0,l1);
            *(__nv_bfloat162*)&ctxHi[i1] = __nv_bfloat162(h2,h3);
            *(__nv_bfloat162*)&ctxLo[i1] = __nv_bfloat162(l2,l3);
        }
    }
}

// ---------------- mma.sync GEMM (BK=64, 2-stage cp.async, ldmatrix) ----------------
enum { EPI_PLAIN=0, EPI_GELU=1, EPI_QKV3=2 };

template<int BM_, int BN_, int NT, int EPI>
__global__ __launch_bounds__(NT, (NT==256)?2:1) void mma_gemm(
    const bf* __restrict__ Ahi, const bf* __restrict__ Alo,
    const bf* __restrict__ Bhi, const bf* __restrict__ Blo,
    int K, int lda, int ldb,
    const float* __restrict__ bias, const float* __restrict__ bias2, const float* __restrict__ bias3,
    float* __restrict__ outF,
    bf* __restrict__ outHi, bf* __restrict__ outLo,
    bf* __restrict__ out2Hi, bf* __restrict__ out2Lo,
    bf* __restrict__ out3Hi, bf* __restrict__ out3Lo,
    int ldc)
{
    constexpr int NWARPS = NT/32;
    constexpr int WGM = BM_/32;
    constexpr int WGN = NWARPS/WGM;
    constexpr int WN  = BN_/WGN;          // 64 or 32
    constexpr int MT  = 2;
    constexpr int NTT = WN/8;             // 8 or 4
    constexpr int NG  = NTT/2;            // 4 or 2
    constexpr int RSTEP = NT/8;           // rows per loader iteration
    constexpr int A_HI = 0;
    constexpr int A_LO = BM_*128;
    constexpr int B_HI = 2*BM_*128;
    constexpr int B_LO = 2*BM_*128 + BN_*128;
    constexpr int STAGE = 2*BM_*128 + 2*BN_*128;
    static_assert(BM_ % RSTEP == 0 && BN_ % RSTEP == 0, "loader tiling");

    extern __shared__ __align__(16) char smem0[];
    const uint32_t sb0 = smem_u32(smem0);
    const uint32_t sbase = (sb0 + 127u) & ~127u;     // 128-aligned base
    char* smem = smem0 + (sbase - sb0);

    const int tid = threadIdx.x, lane = tid & 31, warp = tid >> 5;
    const int warpM = warp / WGN, warpN = warp % WGN;
    const int mBase = blockIdx.y * BM_, nBase = blockIdx.x * BN_;

    // branch-free loader state (computed once)
    const int lr = tid >> 3, lc = tid & 7;
    const uint32_t dsw = (uint32_t)(lr*128) + (uint32_t)((lc*16) ^ ((lr&7)<<4));
    const bf* bAh = Ahi + (long)(mBase + lr)*lda + lc*8;
    const bf* bAl = Alo + (long)(mBase + lr)*lda + lc*8;
    const bf* bBh = Bhi + (long)(nBase + lr)*ldb + lc*8;
    const bf* bBl = Blo + (long)(nBase + lr)*ldb + lc*8;
    const long astep = (long)RSTEP*lda, bstep = (long)RSTEP*ldb;

    auto issue = [&](int c){
        const int k0 = c << 6;
        const uint32_t segbase = sbase + (uint32_t)((c & 1) * STAGE);
        const bf* s; uint32_t d;
        s = bAh + k0; d = segbase + A_HI + dsw;
#pragma unroll
        for (int k=0;k<BM_/RSTEP;k++){ cp16(d, s); s += astep; d += RSTEP*128; }
        s = bAl + k0; d = segbase + A_LO + dsw;
#pragma unroll
        for (int k=0;k<BM_/RSTEP;k++){ cp16(d, s); s += astep; d += RSTEP*128; }
        s = bBh + k0; d = segbase + B_HI + dsw;
#pragma unroll
        for (int k=0;k<BN_/RSTEP;k++){ cp16(d, s); s += bstep; d += RSTEP*128; }
        s = bBl + k0; d = segbase + B_LO + dsw;
#pragma unroll
        for (int k=0;k<BN_/RSTEP;k++){ cp16(d, s); s += bstep; d += RSTEP*128; }
        CP_COMMIT();
    };

    float acc[MT][NTT][4];
#pragma unroll
    for (int i=0;i<MT;i++)
#pragma unroll
        for (int j=0;j<NTT;j++)
#pragma unroll
            for (int e=0;e<4;e++) acc[i][j][e] = 0.f;

    const int lt  = lane >> 3;
    const int lrow = ((lt & 1) << 3) + (lane & 7);
    const int lcol = (lt >> 1) << 4;

    // per-thread ldsm base offsets within a stage (kk=0); addr(kk) = base ^ (kk<<5)
    uint32_t oA[MT], oB[NG];
#pragma unroll
    for (int mt = 0; mt < MT; ++mt){
        int r = warpM*32 + mt*16 + lrow;
        oA[mt] = (uint32_t)(A_HI + r*128) + (uint32_t)(lcol ^ ((r&7)<<4));
    }
#pragma unroll
    for (int g = 0; g < NG; ++g){
        int r = warpN*WN + g*16 + lrow;
        oB[g] = (uint32_t)(B_HI + r*128) + (uint32_t)(lcol ^ ((r&7)<<4));
    }

    const int CH = K >> 6;
    issue(0);

    for (int c = 0; c < CH; ++c){
        if (c + 1 < CH) { issue(c + 1); CP_WAIT(1); }
        else            { CP_WAIT(0); }
        __syncthreads();

        const uint32_t st = sbase + (uint32_t)((c & 1) * STAGE);
        uint32_t aAh_[MT], aAl_[MT], aBh_[NG], aBl_[NG];
#pragma unroll
        for (int mt = 0; mt < MT; ++mt){
            aAh_[mt] = st + oA[mt];
            aAl_[mt] = aAh_[mt] + (A_LO - A_HI);
        }
#pragma unroll
        for (int g = 0; g < NG; ++g){
            aBh_[g] = st + oB[g];
            aBl_[g] = aBh_[g] + (B_LO - B_HI);
        }
#pragma unroll
        for (int kk = 0; kk < 4; ++kk){
            const uint32_t kb = (uint32_t)(kk << 5);
            uint32_t ah[MT][4], al[MT][4];
#pragma unroll
            for (int mt = 0; mt < MT; ++mt){
                ldsm4(ah[mt], aAh_[mt] ^ kb);
                ldsm4(al[mt], aAl_[mt] ^ kb);
            }
#pragma unroll
            for (int g = 0; g < NG; ++g){
                uint32_t bh[4], bl[4];
                ldsm4(bh, aBh_[g] ^ kb);
                ldsm4(bl, aBl_[g] ^ kb);
#pragma unroll
                for (int mt = 0; mt < MT; ++mt)
#pragma unroll
                    for (int sH = 0; sH < 2; ++sH)
                        mma16816(acc[mt][g*2+sH], ah[mt], bh[sH], bh[sH+2]);
#pragma unroll
                for (int mt = 0; mt < MT; ++mt)
#pragma unroll
                    for (int sH = 0; sH < 2; ++sH)
                        mma16816(acc[mt][g*2+sH], ah[mt], bl[sH], bl[sH+2]);
#pragma unroll
                for (int mt = 0; mt < MT; ++mt)
#pragma unroll
                    for (int sH = 0; sH < 2; ++sH)
                        mma16816(acc[mt][g*2+sH], al[mt], bh[sH], bh[sH+2]);
            }
        }
        __syncthreads();
    }

    // epilogue via padded smem
    float* sD = (float*)smem;
    constexpr int LDD = BN_ + 1;
#pragma unroll
    for (int mt = 0; mt < MT; ++mt)
#pragma unroll
        for (int nt = 0; nt < NTT; ++nt){
            int r0 = warpM*32 + mt*16 + (lane >> 2);
            int c0 = warpN*WN + nt*8 + (lane & 3)*2;
            sD[r0*LDD + c0]       = acc[mt][nt][0];
            sD[r0*LDD + c0 + 1]   = acc[mt][nt][1];
            sD[(r0+8)*LDD + c0]   = acc[mt][nt][2];
            sD[(r0+8)*LDD + c0+1] = acc[mt][nt][3];
        }
    __syncthreads();

    if (EPI == EPI_QKV3){
        const int which = nBase / HID;
        const int nloc0 = nBase - which*HID;
        const float* bs = (which==0) ? bias : (which==1) ? bias2 : bias3;
        bf* oHi = (which==0) ? outHi : (which==1) ? out2Hi : out3Hi;
        bf* oLo = (which==0) ? outLo : (which==1) ? out2Lo : out3Lo;
        if (which < 2){
            constexpr int NQ = BN_/4;
            for (int t = tid; t < BM_*NQ; t += NT){
                int m = t / NQ, nq = t % NQ;
                int nl = nloc0 + nq*4;
                int mg = mBase + m, b_ = mg >> 9, sidx = mg & 511;
                int h = nl >> 6, dd = nl & 63;
                float e[4];
#pragma unroll
                for (int j=0;j<4;j++) e[j] = sD[m*LDD + nq*4 + j] + bs[nl+j];
                bf h0,h1,h2,h3,l0,l1,l2,l3;
                bsplit(e[0],h0,l0); bsplit(e[1],h1,l1);
                bsplit(e[2],h2,l2); bsplit(e[3],h3,l3);
                long idx = ((long)(b_*NHEADS + h)*SEQ + sidx)*HDIM + dd;
                *(__nv_bfloat162*)&oHi[idx]   = __nv_bfloat162(h0,h1);
                *(__nv_bfloat162*)&oHi[idx+2] = __nv_bfloat162(h2,h3);
                *(__nv_bfloat162*)&oLo[idx]   = __nv_bfloat162(l0,l1);
                *(__nv_bfloat162*)&oLo[idx+2] = __nv_bfloat162(l2,l3);
            }
        } else {
            for (int t = tid; t < BM_*BN_; t += NT){
                int m = t & (BM_-1), n = t / BM_;
                int nl = nloc0 + n, h = nl >> 6, dd = nl & 63;
                int mg = mBase + m, b_ = mg >> 9, sidx = mg & 511;
                float v = sD[m*LDD + n] + bs[nl];
                bf hh, ll; bsplit(v, hh, ll);
                long idx = ((long)(b_*NHEADS + h)*HDIM + dd)*SEQ + sidx;
                oHi[idx] = hh; oLo[idx] = ll;
            }
        }
    } else {
        constexpr int NQ = BN_ / 4;
        for (int t = tid; t < BM_*NQ; t += NT){
            int m = t / NQ, nq = t % NQ;
            int n0 = nBase + nq*4;
            int mg = mBase + m;
            float e[4];
#pragma unroll
            for (int j=0;j<4;j++) e[j] = sD[m*LDD + nq*4 + j];
            if (EPI == EPI_PLAIN){
#pragma unroll
                for (int j=0;j<4;j++) e[j] += bias[n0+j];
                float4 v = {e[0],e[1],e[2],e[3]};
                *(float4*)&outF[(long)mg*ldc + n0] = v;
            } else { // EPI_GELU
#pragma unroll
                for (int j=0;j<4;j++){
                    float t2 = e[j] + bias[n0+j];
                    e[j] = 0.5f*t2*(1.f + erff(t2*0.70710678118654752f));
                }
                bf h0,h1,h2,h3,l0,l1,l2,l3;
                bsplit(e[0],h0,l0); bsplit(e[1],h1,l1);
                bsplit(e[2],h2,l2); bsplit(e[3],h3,l3);
                long idx = (long)mg*ldc + n0;
                *(__nv_bfloat162*)&outHi[idx]   = __nv_bfloat162(h0,h1);
                *(__nv_bfloat162*)&outHi[idx+2] = __nv_bfloat162(h2,h3);
                *(__nv_bfloat162*)&outLo[idx]   = __nv_bfloat162(l0,l1);
                *(__nv_bfloat162*)&outLo[idx+2] = __nv_bfloat162(l2,l3);
            }
        }
    }
}

// ---------------- host ----------------
#define SMEM_BIG  196736   // 2 stages * 96KB + 128 align pad
#define SMEM_SML  98432    // 2 stages * 48KB + 128 align pad; 2 CTAs/SM

extern "C" void kernel_launch(void* const* d_in, const int* in_sizes, int n_in,
                              void* d_out, int out_size)
{
    const float* emb     = (const float*)d_in[0];
    const int*   seg     = (const int*)  d_in[1];
    const float* rel_emb = (const float*)d_in[2];
    const float* Wq = (const float*)d_in[3];  const float* bq = (const float*)d_in[4];
    const float* Wk = (const float*)d_in[5];  const float* bk = (const float*)d_in[6];
    const float* Wv = (const float*)d_in[7];  const float* bv = (const float*)d_in[8];
    const float* Wo = (const float*)d_in[9];  const float* bo = (const float*)d_in[10];
    const float* ln1_g = (const float*)d_in[11]; const float* ln1_b = (const float*)d_in[12];
    const float* W1 = (const float*)d_in[13]; const float* b1 = (const float*)d_in[14];
    const float* W2 = (const float*)d_in[15]; const float* b2 = (const float*)d_in[16];
    const float* ln2_g = (const float*)d_in[17]; const float* ln2_b = (const float*)d_in[18];
    float* out = (float*)d_out;

    static bool inited = false;
    static float *hid, *tmp, *pb, *mk;
    static bf *hA_h,*hA_l,*q_h,*q_l,*k_h,*k_l,*vt_h,*vt_l,*cx_h,*cx_l,*ff_h,*ff_l;
    static bf *wqkv_h,*wqkv_l,*wo_h,*wo_l,*w1_h,*w1_l,*w2_h,*w2_l;
    if (!inited){
        inited = true;
        cudaGetSymbolAddress((void**)&hid, g_hidden);
        cudaGetSymbolAddress((void**)&tmp, g_tmp);
        cudaGetSymbolAddress((void**)&pb,  g_pb);
        cudaGetSymbolAddress((void**)&mk,  g_mask);
        cudaGetSymbolAddress((void**)&hA_h, g_hidA_hi); cudaGetSymbolAddress((void**)&hA_l, g_hidA_lo);
        cudaGetSymbolAddress((void**)&q_h,  g_q_hi);    cudaGetSymbolAddress((void**)&q_l,  g_q_lo);
        cudaGetSymbolAddress((void**)&k_h,  g_k_hi);    cudaGetSymbolAddress((void**)&k_l,  g_k_lo);
        cudaGetSymbolAddress((void**)&vt_h, g_vt_hi);   cudaGetSymbolAddress((void**)&vt_l, g_vt_lo);
        cudaGetSymbolAddress((void**)&cx_h, g_ctx_hi);  cudaGetSymbolAddress((void**)&cx_l, g_ctx_lo);
        cudaGetSymbolAddress((void**)&ff_h, g_ff_hi);   cudaGetSymbolAddress((void**)&ff_l, g_ff_lo);
        cudaGetSymbolAddress((void**)&wqkv_h, g_WqkvT_hi); cudaGetSymbolAddress((void**)&wqkv_l, g_WqkvT_lo);
        cudaGetSymbolAddress((void**)&wo_h, g_WoT_hi);  cudaGetSymbolAddress((void**)&wo_l, g_WoT_lo);
        cudaGetSymbolAddress((void**)&w1_h, g_W1T_hi);  cudaGetSymbolAddress((void**)&w1_l, g_W1T_lo);
        cudaGetSymbolAddress((void**)&w2_h, g_W2T_hi);  cudaGetSymbolAddress((void**)&w2_l, g_W2T_lo);
        cudaFuncSetAttribute(mma_gemm<128,256,512,EPI_QKV3>, cudaFuncAttributeMaxDynamicSharedMemorySize, SMEM_BIG);
        cudaFuncSetAttribute(mma_gemm<128,256,512,EPI_GELU>, cudaFuncAttributeMaxDynamicSharedMemorySize, SMEM_BIG);
        cudaFuncSetAttribute(mma_gemm<64,128,256,EPI_PLAIN>, cudaFuncAttributeMaxDynamicSharedMemorySize, SMEM_SML);
        cudaFuncSetAttribute(flash_k, cudaFuncAttributeMaxDynamicSharedMemorySize, FLASH_SMEM);
    }

    // ---- setup: QKV GEMM stays at my launch index 3 ----
    tsplit_qkv_k<<<dim3(HID/32, HID/32, 3), dim3(32,8)>>>(Wq, Wk, Wv, wqkv_h, wqkv_l);     // 0
    split_copy_k<<<(ROWS*HID+255)/256, 256>>>(emb, hid, hA_h, hA_l, ROWS*HID);             // 1
    tsplit_k<<<dim3(HID/32, HID/32),   dim3(32,8)>>>(Wo, wo_h, wo_l, HID, HID);            // 2
    mma_gemm<128,256,512,EPI_QKV3><<<dim3(9,32,1),512,SMEM_BIG>>>(                          // 3
        hA_h,hA_l, wqkv_h,wqkv_l, HID, HID, HID,
        bq, bk, bv, nullptr, q_h,q_l, k_h,k_l, vt_h,vt_l, 0);
    mask_k<<<(ROWS+255)/256, 256>>>(seg, mk);
    posbias_k<<<(SEQ*SEQ+255)/256, 256>>>(rel_emb, pb);
    tsplit_k<<<dim3(FFDIM/32, HID/32), dim3(32,8)>>>(W1, w1_h, w1_l, HID, FFDIM);
    tsplit_k<<<dim3(HID/32, FFDIM/32), dim3(32,8)>>>(W2, w2_h, w2_l, FFDIM, HID);

    for (int L=0; L<NLAYERS; L++){
        if (L > 0)
            mma_gemm<128,256,512,EPI_QKV3><<<dim3(9,32,1),512,SMEM_BIG>>>(
                hA_h,hA_l, wqkv_h,wqkv_l, HID, HID, HID,
                bq, bk, bv, nullptr, q_h,q_l, k_h,k_l, vt_h,vt_l, 0);

        // fused attention
        flash_k<<<dim3(4, NBH), 512, FLASH_SMEM>>>(
            q_h,q_l, k_h,k_l, vt_h,vt_l, pb, mk, cx_h, cx_l);

        // O projection (64x128, 2 CTAs/SM)
        mma_gemm<64,128,256,EPI_PLAIN><<<dim3(6,64,1),256,SMEM_SML>>>(
            cx_h,cx_l, wo_h,wo_l, HID, HID, HID,
            bo,nullptr,nullptr, tmp, nullptr,nullptr, nullptr,nullptr, nullptr,nullptr, HID);
        resln_k<<<ROWS,256>>>(hid, tmp, ln1_g, ln1_b, hid, hA_h, hA_l);

        // FF1 (GELU), 128x256
        mma_gemm<128,256,512,EPI_GELU><<<dim3(12,32,1),512,SMEM_BIG>>>(
            hA_h,hA_l, w1_h,w1_l, HID, HID, HID,
            b1,nullptr,nullptr, nullptr, ff_h,ff_l, nullptr,nullptr, nullptr,nullptr, FFDIM);
        // FF2 (64x128, 2 CTAs/SM)
        mma_gemm<64,128,256,EPI_PLAIN><<<dim3(6,64,1),256,SMEM_SML>>>(
            ff_h,ff_l, w2_h,w2_l, FFDIM, FFDIM, FFDIM,
            b2,nullptr,nullptr, tmp, nullptr,nullptr, nullptr,nullptr, nullptr,nullptr, HID);
        resln_k<<<ROWS,256>>>(hid, tmp, ln2_g, ln2_b, (L==NLAYERS-1) ? out : hid, hA_h, hA_l);
    }
}

// round 17
// speedup vs baseline: 1.0376x; 1.0376x over previous
#include <cuda_runtime.h>
#include <cuda_bf16.h>
#include <math.h>
#include <stdint.h>

// ---------------- constants ----------------
#define BATCH   8
#define SEQ     512
#define HID     768
#define NHEADS  12
#define HDIM    64
#define FFDIM   3072
#define NLAYERS 12
#define ROWS    (BATCH*SEQ)          // 4096
#define NBH     (BATCH*NHEADS)       // 96

typedef __nv_bfloat16 bf;

// ---------------- scratch (device globals; allocation-free) ----------------
__device__ float g_hidden[ROWS*HID];
__device__ float g_tmp   [ROWS*HID];
__device__ float g_pb    [NHEADS*SEQ*SEQ];
__device__ float g_mask  [ROWS];

__device__ bf g_hidA_hi[ROWS*HID], g_hidA_lo[ROWS*HID];
__device__ bf g_q_hi [ROWS*HID], g_q_lo [ROWS*HID];   // [B,H,S,64]
__device__ bf g_k_hi [ROWS*HID], g_k_lo [ROWS*HID];   // [B,H,S,64]
__device__ bf g_vt_hi[ROWS*HID], g_vt_lo[ROWS*HID];   // [B,H,64,S]
__device__ bf g_ctx_hi[ROWS*HID], g_ctx_lo[ROWS*HID]; // [B*S,768]
__device__ bf g_ff_hi[ROWS*FFDIM], g_ff_lo[ROWS*FFDIM];

__device__ bf g_WqkvT_hi[3*HID*HID], g_WqkvT_lo[3*HID*HID];  // [2304,768]
__device__ bf g_WoT_hi[HID*HID],  g_WoT_lo[HID*HID];
__device__ bf g_W1T_hi[HID*FFDIM], g_W1T_lo[HID*FFDIM]; // [3072,768]
__device__ bf g_W2T_hi[HID*FFDIM], g_W2T_lo[HID*FFDIM]; // [768,3072]

// ---------------- PTX helpers (sm_100 baseline only) ----------------
__device__ __forceinline__ uint32_t smem_u32(const void* p){
    uint32_t a;
    asm("{ .reg .u64 t; cvta.to.shared.u64 t, %1; cvt.u32.u64 %0, t; }" : "=r"(a) : "l"(p));
    return a;
}
__device__ __forceinline__ void cp16(uint32_t dst, const void* src){
    asm volatile("cp.async.cg.shared.global [%0], [%1], 16;" :: "r"(dst), "l"(src));
}
#define CP_COMMIT() asm volatile("cp.async.commit_group;" ::: "memory")
#define CP_WAIT(n)  asm volatile("cp.async.wait_group %0;" :: "n"(n) : "memory")

__device__ __forceinline__ void ldsm4(uint32_t* r, uint32_t addr){
    asm volatile("ldmatrix.sync.aligned.m8n8.x4.shared.b16 {%0,%1,%2,%3}, [%4];"
                 : "=r"(r[0]), "=r"(r[1]), "=r"(r[2]), "=r"(r[3]) : "r"(addr));
}

__device__ __forceinline__ void mma16816(float* d, const uint32_t* a,
                                         uint32_t b0, uint32_t b1){
    asm volatile(
        "mma.sync.aligned.m16n8k16.row.col.f32.bf16.bf16.f32 "
        "{%0,%1,%2,%3}, {%4,%5,%6,%7}, {%8,%9}, {%0,%1,%2,%3};"
        : "+f"(d[0]), "+f"(d[1]), "+f"(d[2]), "+f"(d[3])
        : "r"(a[0]), "r"(a[1]), "r"(a[2]), "r"(a[3]), "r"(b0), "r"(b1));
}

__device__ __forceinline__ void bsplit(float v, bf& h, bf& l){
    h = __float2bfloat16(v);
    l = __float2bfloat16(v - __bfloat162float(h));
}

// ---------------- reductions ----------------
__device__ __forceinline__ float warpSum(float v){
#pragma unroll
    for (int o=16;o>0;o>>=1) v += __shfl_xor_sync(0xffffffffu, v, o);
    return v;
}
__device__ float blockSum(float v){
    __shared__ float sh[8];
    __shared__ float total;
    int lane = threadIdx.x & 31, wid = threadIdx.x >> 5;
    v = warpSum(v);
    __syncthreads();
    if (lane == 0) sh[wid] = v;
    __syncthreads();
    if (wid == 0){
        float r = (lane < 8) ? sh[lane] : 0.f;
        r = warpSum(r);
        if (lane == 0) total = r;
    }
    __syncthreads();
    return total;
}

// ---------------- small kernels ----------------
__global__ void split_copy_k(const float* __restrict__ src, float* __restrict__ dstF,
                             bf* __restrict__ hi, bf* __restrict__ lo, int n){
    int i = blockIdx.x*blockDim.x + threadIdx.x;
    if (i >= n) return;
    float v = src[i];
    dstF[i] = v;
    bf h, l; bsplit(v, h, l);
    hi[i] = h; lo[i] = l;
}

__global__ void mask_k(const int* __restrict__ seg, float* __restrict__ mask){
    int i = blockIdx.x*blockDim.x + threadIdx.x;
    if (i < ROWS) mask[i] = (seg[i] > 0) ? 0.f : -10000.f;
}

__device__ __forceinline__ int rel_bucket(int qpos, int kpos){
    int rel = kpos - qpos;
    int off = (rel > 0) ? 16 : 0;
    int ar  = rel < 0 ? -rel : rel;
    if (ar < 8) return off + ar;
    float t = logf((float)ar / 8.0f) / 2.772588722239781f * 8.0f;
    int v = 8 + (int)t;
    if (v > 15) v = 15;
    return off + v;
}

__global__ void posbias_k(const float* __restrict__ rel_emb, float* __restrict__ pb){
    int idx = blockIdx.x*blockDim.x + threadIdx.x;
    if (idx >= SEQ*SEQ) return;
    int q = idx >> 9, k = idx & 511;
    int bkt = rel_bucket(q, k);
#pragma unroll
    for (int h=0; h<NHEADS; h++)
        pb[((long)h*SEQ + q)*SEQ + k] = rel_emb[bkt*NHEADS + h];
}

// W[K,N] fp32 -> WT hi/lo [N,K] bf16
__global__ void tsplit_k(const float* __restrict__ W,
                         bf* __restrict__ Thi, bf* __restrict__ Tlo,
                         int K, int N){
    __shared__ float t[32][33];
    int k0 = blockIdx.y*32, n0 = blockIdx.x*32;
    int x = threadIdx.x, y = threadIdx.y;
#pragma unroll
    for (int i=y; i<32; i+=8) t[i][x] = W[(long)(k0+i)*N + n0 + x];
    __syncthreads();
#pragma unroll
    for (int i=y; i<32; i+=8){
        float v = t[x][i];
        bf h, l; bsplit(v, h, l);
        long o = (long)(n0+i)*K + k0 + x;
        Thi[o] = h; Tlo[o] = l;
    }
}

// fused QKV-weight transpose-split: grid.z selects Wq/Wk/Wv
__global__ void tsplit_qkv_k(const float* __restrict__ Wq, const float* __restrict__ Wk,
                             const float* __restrict__ Wv,
                             bf* __restrict__ Thi, bf* __restrict__ Tlo){
    __shared__ float t[32][33];
    const float* W = (blockIdx.z==0) ? Wq : (blockIdx.z==1) ? Wk : Wv;
    bf* Th = Thi + (long)blockIdx.z*HID*HID;
    bf* Tl = Tlo + (long)blockIdx.z*HID*HID;
    int k0 = blockIdx.y*32, n0 = blockIdx.x*32;
    int x = threadIdx.x, y = threadIdx.y;
#pragma unroll
    for (int i=y; i<32; i+=8) t[i][x] = W[(long)(k0+i)*HID + n0 + x];
    __syncthreads();
#pragma unroll
    for (int i=y; i<32; i+=8){
        float v = t[x][i];
        bf h, l; bsplit(v, h, l);
        long o = (long)(n0+i)*HID + k0 + x;
        Th[o] = h; Tl[o] = l;
    }
}

__global__ __launch_bounds__(256) void resln_k(
    const float* __restrict__ resid, const float* __restrict__ x,
    const float* __restrict__ g, const float* __restrict__ b,
    float* __restrict__ out,
    bf* __restrict__ ohi, bf* __restrict__ olo)
{
    long base = (long)blockIdx.x * HID;
    int t = threadIdx.x;
    float v[3]; float s = 0.f;
#pragma unroll
    for (int i=0;i<3;i++){ v[i] = resid[base + t + 256*i] + x[base + t + 256*i]; s += v[i]; }
    s = blockSum(s);
    float mean = s * (1.f/768.f);
    float q = 0.f;
#pragma unroll
    for (int i=0;i<3;i++){ float d = v[i]-mean; q += d*d; }
    q = blockSum(q);
    float inv = 1.f / sqrtf(q*(1.f/768.f) + 1e-6f);
#pragma unroll
    for (int i=0;i<3;i++){
        int c = t + 256*i;
        float r = g[c]*(v[i]-mean)*inv + b[c];
        out[base + c] = r;
        bf h, l; bsplit(r, h, l);
        ohi[base + c] = h; olo[base + c] = l;
    }
}

// ---------------- fused flash attention ----------------
#define FLASH_SMEM 167936

__global__ __launch_bounds__(512,1) void flash_k(
    const bf* __restrict__ Qh, const bf* __restrict__ Ql,
    const bf* __restrict__ Kh, const bf* __restrict__ Kl,
    const bf* __restrict__ Vth, const bf* __restrict__ Vtl,
    const float* __restrict__ pbias, const float* __restrict__ mk,
    bf* __restrict__ ctxHi, bf* __restrict__ ctxLo)
{
    constexpr int Q_HI=0, Q_LO=16384, K_HI=32768, K_LO=49152;
    constexpr int V_HI=65536, V_LO=81920, P_HI=98304, P_LO=131072;
    constexpr int REDM=163840, REDS=165888;
    extern __shared__ __align__(16) char smem[];
    const uint32_t sb = smem_u32(smem);
    float* redM = (float*)(smem + REDM);
    float* redS = (float*)(smem + REDS);

    const int tid=threadIdx.x, lane=tid&31, warp=tid>>5;
    const int warpM = warp>>2, warpN = warp&3;
    const int q0 = blockIdx.x*128, bh = blockIdx.y;
    const int b = bh/NHEADS, h = bh - b*NHEADS;
    const long baseQK = (long)bh*SEQ*HDIM;
    const long baseV  = (long)bh*HDIM*SEQ;

    const int lt = lane>>3, lrow = ((lt&1)<<3)+(lane&7), lcol = (lt>>1)<<4;
    const int qr = lane>>2, qc = (lane&3)*2;

    // Q load (once) — branch-free, strength-reduced
    {
        const int rk = tid>>3, ck = tid&7;
        const uint32_t dsw = (uint32_t)(rk*128) + (uint32_t)((ck*16)^((rk&7)<<4));
        const bf* sQh = Qh + baseQK + (long)(q0+rk)*HDIM + ck*8;
        const bf* sQl = Ql + baseQK + (long)(q0+rk)*HDIM + ck*8;
        uint32_t d = sb + Q_HI + dsw;
#pragma unroll
        for (int k=0;k<2;k++){ cp16(d, sQh); sQh += 64*HDIM; d += 64*128; }
        d = sb + Q_LO + dsw;
#pragma unroll
        for (int k=0;k<2;k++){ cp16(d, sQl); sQl += 64*HDIM; d += 64*128; }
    }
    // persistent, sequentially-advanced KV loader pointers (loadKV called j=0,1,2,3 in order)
    const int rk = tid>>3, ck = tid&7;
    const uint32_t dswk = (uint32_t)(rk*128) + (uint32_t)((ck*16)^((rk&7)<<4));
    const bf* pKh = Kh + baseQK + (long)rk*HDIM + ck*8;
    const bf* pKl = Kl + baseQK + (long)rk*HDIM + ck*8;
    const int rv = tid>>4, cv = tid&15;
    const uint32_t dswv = (uint32_t)(rv*256) + (uint32_t)((cv*16)^((rv&7)<<4));
    const bf* pVh = Vth + baseV + (long)rv*SEQ + cv*8;
    const bf* pVl = Vtl + baseV + (long)rv*SEQ + cv*8;

    auto loadKV = [&](){
        const bf* s; uint32_t d;
        s = pKh; d = sb + K_HI + dswk;
#pragma unroll
        for (int k=0;k<2;k++){ cp16(d, s); s += 64*HDIM; d += 64*128; }
        s = pKl; d = sb + K_LO + dswk;
#pragma unroll
        for (int k=0;k<2;k++){ cp16(d, s); s += 64*HDIM; d += 64*128; }
        s = pVh; d = sb + V_HI + dswv;
#pragma unroll
        for (int k=0;k<2;k++){ cp16(d, s); s += 32*SEQ; d += 32*256; }
        s = pVl; d = sb + V_LO + dswv;
#pragma unroll
        for (int k=0;k<2;k++){ cp16(d, s); s += 32*SEQ; d += 32*256; }
        CP_COMMIT();
        pKh += 128*HDIM; pKl += 128*HDIM;   // next 128 K-rows
        pVh += 128;      pVl += 128;        // next 128 s-columns
    };
    loadKV();

    float m_run[4], l_run[4];
#pragma unroll
    for (int i=0;i<4;i++){ m_run[i] = -3.0e38f; l_run[i] = 0.f; }
    float oacc[2][2][4];
#pragma unroll
    for (int mt=0;mt<2;mt++)
#pragma unroll
        for (int nt=0;nt<2;nt++)
#pragma unroll
            for (int e=0;e<4;e++) oacc[mt][nt][e] = 0.f;

    for (int j=0;j<4;j++){
        CP_WAIT(0); __syncthreads();

        float acc[2][4][4];
#pragma unroll
        for (int mt=0;mt<2;mt++)
#pragma unroll
            for (int nt=0;nt<4;nt++)
#pragma unroll
                for (int e=0;e<4;e++) acc[mt][nt][e] = 0.f;
#pragma unroll
        for (int kk=0;kk<4;kk++){
            const uint32_t kb = (uint32_t)(kk<<5);
            uint32_t ah[2][4], al[2][4];
#pragma unroll
            for (int mt=0;mt<2;mt++){
                int r = warpM*32 + mt*16 + lrow;
                uint32_t cb = (kb + lcol) ^ ((uint32_t)(r&7)<<4);
                ldsm4(ah[mt], sb + Q_HI + r*128 + cb);
                ldsm4(al[mt], sb + Q_LO + r*128 + cb);
            }
            uint32_t bhf[2][4], blf[2][4];
#pragma unroll
            for (int g=0; g<2; g++){
                int r = warpN*32 + g*16 + lrow;
                uint32_t cb = (kb + lcol) ^ ((uint32_t)(r&7)<<4);
                ldsm4(bhf[g], sb + K_HI + r*128 + cb);
                ldsm4(blf[g], sb + K_LO + r*128 + cb);
            }
#pragma unroll
            for (int mt=0;mt<2;mt++)
#pragma unroll
                for (int nt=0;nt<4;nt++)
                    mma16816(acc[mt][nt], ah[mt], bhf[nt>>1][nt&1], bhf[nt>>1][(nt&1)+2]);
#pragma unroll
            for (int mt=0;mt<2;mt++)
#pragma unroll
                for (int nt=0;nt<4;nt++)
                    mma16816(acc[mt][nt], ah[mt], blf[nt>>1][nt&1], blf[nt>>1][(nt&1)+2]);
#pragma unroll
            for (int mt=0;mt<2;mt++)
#pragma unroll
                for (int nt=0;nt<4;nt++)
                    mma16816(acc[mt][nt], al[mt], bhf[nt>>1][nt&1], bhf[nt>>1][(nt&1)+2]);
        }

        float pmax[4] = {-3.0e38f,-3.0e38f,-3.0e38f,-3.0e38f};
#pragma unroll
        for (int mt=0;mt<2;mt++){
            int r0 = q0 + warpM*32 + mt*16 + qr;
            const float* pbr0 = pbias + ((long)h*SEQ + r0)*SEQ;
            const float* pbr1 = pbr0 + 8*SEQ;
#pragma unroll
            for (int nt=0;nt<4;nt++){
                int col = j*128 + warpN*32 + nt*8 + qc;
                float2 p0 = *(const float2*)(pbr0 + col);
                float2 p1 = *(const float2*)(pbr1 + col);
                float2 mv = *(const float2*)(mk + b*SEQ + col);
                acc[mt][nt][0] = acc[mt][nt][0]*0.125f + p0.x + mv.x;
                acc[mt][nt][1] = acc[mt][nt][1]*0.125f + p0.y + mv.y;
                acc[mt][nt][2] = acc[mt][nt][2]*0.125f + p1.x + mv.x;
                acc[mt][nt][3] = acc[mt][nt][3]*0.125f + p1.y + mv.y;
                pmax[mt*2]   = fmaxf(pmax[mt*2],   fmaxf(acc[mt][nt][0], acc[mt][nt][1]));
                pmax[mt*2+1] = fmaxf(pmax[mt*2+1], fmaxf(acc[mt][nt][2], acc[mt][nt][3]));
            }
        }
#pragma unroll
        for (int ri=0;ri<4;ri++){
            pmax[ri] = fmaxf(pmax[ri], __shfl_xor_sync(0xffffffffu, pmax[ri], 1));
            pmax[ri] = fmaxf(pmax[ri], __shfl_xor_sync(0xffffffffu, pmax[ri], 2));
        }
        if ((lane&3)==0){
#pragma unroll
            for (int ri=0;ri<4;ri++){
                int rl = warpM*32 + (ri>>1)*16 + qr + (ri&1)*8;
                redM[rl*4 + warpN] = pmax[ri];
            }
        }
        __syncthreads();

        float alpha[4];
#pragma unroll
        for (int ri=0;ri<4;ri++){
            int rl = warpM*32 + (ri>>1)*16 + qr + (ri&1)*8;
            float tm = fmaxf(fmaxf(redM[rl*4],redM[rl*4+1]), fmaxf(redM[rl*4+2],redM[rl*4+3]));
            float mn = fmaxf(m_run[ri], tm);
            alpha[ri] = expf(m_run[ri] - mn);
            m_run[ri] = mn;
        }

        float psum[4] = {0.f,0.f,0.f,0.f};
#pragma unroll
        for (int mt=0;mt<2;mt++){
            int rl0 = warpM*32 + mt*16 + qr;
            int rl1 = rl0 + 8;
#pragma unroll
            for (int nt=0;nt<4;nt++){
                float e0 = expf(acc[mt][nt][0] - m_run[mt*2]);
                float e1 = expf(acc[mt][nt][1] - m_run[mt*2]);
                float e2 = expf(acc[mt][nt][2] - m_run[mt*2+1]);
                float e3 = expf(acc[mt][nt][3] - m_run[mt*2+1]);
                psum[mt*2]   += e0 + e1;
                psum[mt*2+1] += e2 + e3;
                int colb = (warpN*32 + nt*8 + qc)*2;
                bf h0,l0,h1,l1,h2,l2,h3,l3;
                bsplit(e0,h0,l0); bsplit(e1,h1,l1);
                bsplit(e2,h2,l2); bsplit(e3,h3,l3);
                uint32_t sw0 = (uint32_t)colb ^ ((uint32_t)(rl0&7)<<4);
                uint32_t sw1 = (uint32_t)colb ^ ((uint32_t)(rl1&7)<<4);
                *(__nv_bfloat162*)(smem + P_HI + rl0*256 + sw0) = __nv_bfloat162(h0,h1);
                *(__nv_bfloat162*)(smem + P_LO + rl0*256 + sw0) = __nv_bfloat162(l0,l1);
                *(__nv_bfloat162*)(smem + P_HI + rl1*256 + sw1) = __nv_bfloat162(h2,h3);
                *(__nv_bfloat162*)(smem + P_LO + rl1*256 + sw1) = __nv_bfloat162(l2,l3);
            }
        }
#pragma unroll
        for (int ri=0;ri<4;ri++){
            psum[ri] += __shfl_xor_sync(0xffffffffu, psum[ri], 1);
            psum[ri] += __shfl_xor_sync(0xffffffffu, psum[ri], 2);
        }
        if ((lane&3)==0){
#pragma unroll
            for (int ri=0;ri<4;ri++){
                int rl = warpM*32 + (ri>>1)*16 + qr + (ri&1)*8;
                redS[rl*4 + warpN] = psum[ri];
            }
        }
        __syncthreads();

#pragma unroll
        for (int ri=0;ri<4;ri++){
            int rl = warpM*32 + (ri>>1)*16 + qr + (ri&1)*8;
            float ts = redS[rl*4] + redS[rl*4+1] + redS[rl*4+2] + redS[rl*4+3];
            l_run[ri] = alpha[ri]*l_run[ri] + ts;
        }
#pragma unroll
        for (int mt=0;mt<2;mt++)
#pragma unroll
            for (int nt=0;nt<2;nt++)
#pragma unroll
                for (int e=0;e<4;e++) oacc[mt][nt][e] *= alpha[mt*2 + (e>>1)];

#pragma unroll
        for (int ks=0;ks<8;ks++){
            const uint32_t kb2 = (uint32_t)(ks<<5);
            uint32_t pah[2][4], pal[2][4];
#pragma unroll
            for (int mt=0;mt<2;mt++){
                int r = warpM*32 + mt*16 + lrow;
                uint32_t cb = (kb2 + lcol) ^ ((uint32_t)(r&7)<<4);
                ldsm4(pah[mt], sb + P_HI + r*256 + cb);
                ldsm4(pal[mt], sb + P_LO + r*256 + cb);
            }
            uint32_t vbh[4], vbl[4];
            {
                int n = warpN*16 + lrow;
                uint32_t cb = (kb2 + lcol) ^ ((uint32_t)(n&7)<<4);
                ldsm4(vbh, sb + V_HI + n*256 + cb);
                ldsm4(vbl, sb + V_LO + n*256 + cb);
            }
#pragma unroll
            for (int mt=0;mt<2;mt++)
#pragma unroll
                for (int nt=0;nt<2;nt++)
                    mma16816(oacc[mt][nt], pah[mt], vbh[nt], vbh[nt+2]);
#pragma unroll
            for (int mt=0;mt<2;mt++)
#pragma unroll
                for (int nt=0;nt<2;nt++)
                    mma16816(oacc[mt][nt], pah[mt], vbl[nt], vbl[nt+2]);
#pragma unroll
            for (int mt=0;mt<2;mt++)
#pragma unroll
                for (int nt=0;nt<2;nt++)
                    mma16816(oacc[mt][nt], pal[mt], vbh[nt], vbh[nt+2]);
        }
        __syncthreads();
        if (j < 3) loadKV();
    }

    float inv[4];
#pragma unroll
    for (int ri=0;ri<4;ri++) inv[ri] = 1.f / l_run[ri];
#pragma unroll
    for (int mt=0;mt<2;mt++){
        int m0 = q0 + warpM*32 + mt*16 + qr;
#pragma unroll
        for (int nt=0;nt<2;nt++){
            int col = h*HDIM + warpN*16 + nt*8 + qc;
            long i0 = ((long)(b*SEQ + m0))*HID + col;
            long i1 = i0 + 8L*HID;
            float e0 = oacc[mt][nt][0]*inv[mt*2];
            float e1 = oacc[mt][nt][1]*inv[mt*2];
            float e2 = oacc[mt][nt][2]*inv[mt*2+1];
            float e3 = oacc[mt][nt][3]*inv[mt*2+1];
            bf h0,l0,h1,l1,h2,l2,h3,l3;
            bsplit(e0,h0,l0); bsplit(e1,h1,l1);
            bsplit(e2,h2,l2); bsplit(e3,h3,l3);
            *(__nv_bfloat162*)&ctxHi[i0] = __nv_bfloat162(h0,h1);
            *(__nv_bfloat162*)&ctxLo[i0] = __nv_bfloat162(l0,l1);
            *(__nv_bfloat162*)&ctxHi[i1] = __nv_bfloat162(h2,h3);
            *(__nv_bfloat162*)&ctxLo[i1] = __nv_bfloat162(l2,l3);
        }
    }
}

// ---------------- mma.sync GEMM (BK=64, 2-stage cp.async, ldmatrix) ----------------
enum { EPI_PLAIN=0, EPI_GELU=1, EPI_QKV3=2 };

template<int BM_, int BN_, int NT, int EPI>
__global__ __launch_bounds__(NT, (NT==256)?2:1) void mma_gemm(
    const bf* __restrict__ Ahi, const bf* __restrict__ Alo,
    const bf* __restrict__ Bhi, const bf* __restrict__ Blo,
    int K, int lda, int ldb,
    const float* __restrict__ bias, const float* __restrict__ bias2, const float* __restrict__ bias3,
    float* __restrict__ outF,
    bf* __restrict__ outHi, bf* __restrict__ outLo,
    bf* __restrict__ out2Hi, bf* __restrict__ out2Lo,
    bf* __restrict__ out3Hi, bf* __restrict__ out3Lo,
    int ldc)
{
    constexpr int NWARPS = NT/32;
    constexpr int WGM = BM_/32;
    constexpr int WGN = NWARPS/WGM;
    constexpr int WN  = BN_/WGN;          // 64 or 32
    constexpr int MT  = 2;
    constexpr int NTT = WN/8;             // 8 or 4
    constexpr int NG  = NTT/2;            // 4 or 2
    constexpr int RSTEP = NT/8;           // rows per loader iteration
    constexpr int A_HI = 0;
    constexpr int A_LO = BM_*128;
    constexpr int B_HI = 2*BM_*128;
    constexpr int B_LO = 2*BM_*128 + BN_*128;
    constexpr int STAGE = 2*BM_*128 + 2*BN_*128;
    static_assert(BM_ % RSTEP == 0 && BN_ % RSTEP == 0, "loader tiling");

    extern __shared__ __align__(16) char smem[];
    const uint32_t sbase = smem_u32(smem);

    const int tid = threadIdx.x, lane = tid & 31, warp = tid >> 5;
    const int warpM = warp / WGN, warpN = warp % WGN;
    const int mBase = blockIdx.y * BM_, nBase = blockIdx.x * BN_;

    // persistent, sequentially-advanced loader pointers (issue() called c=0,1,2,... in order)
    const int lr = tid >> 3, lc = tid & 7;
    const uint32_t dsw = (uint32_t)(lr*128) + (uint32_t)((lc*16) ^ ((lr&7)<<4));
    const bf* pAh = Ahi + (long)(mBase + lr)*lda + lc*8;
    const bf* pAl = Alo + (long)(mBase + lr)*lda + lc*8;
    const bf* pBh = Bhi + (long)(nBase + lr)*ldb + lc*8;
    const bf* pBl = Blo + (long)(nBase + lr)*ldb + lc*8;
    const long astep = (long)RSTEP*lda, bstep = (long)RSTEP*ldb;
    uint32_t stg = 0;

    auto issue = [&](){
        const uint32_t segbase = sbase + stg * STAGE;
        const bf* s; uint32_t d;
        s = pAh; d = segbase + A_HI + dsw;
#pragma unroll
        for (int k=0;k<BM_/RSTEP;k++){ cp16(d, s); s += astep; d += RSTEP*128; }
        s = pAl; d = segbase + A_LO + dsw;
#pragma unroll
        for (int k=0;k<BM_/RSTEP;k++){ cp16(d, s); s += astep; d += RSTEP*128; }
        s = pBh; d = segbase + B_HI + dsw;
#pragma unroll
        for (int k=0;k<BN_/RSTEP;k++){ cp16(d, s); s += bstep; d += RSTEP*128; }
        s = pBl; d = segbase + B_LO + dsw;
#pragma unroll
        for (int k=0;k<BN_/RSTEP;k++){ cp16(d, s); s += bstep; d += RSTEP*128; }
        CP_COMMIT();
        pAh += 64; pAl += 64; pBh += 64; pBl += 64;   // next K chunk
        stg ^= 1u;
    };

    float acc[MT][NTT][4];
#pragma unroll
    for (int i=0;i<MT;i++)
#pragma unroll
        for (int j=0;j<NTT;j++)
#pragma unroll
            for (int e=0;e<4;e++) acc[i][j][e] = 0.f;

    const int lt  = lane >> 3;
    const int lrow = ((lt & 1) << 3) + (lane & 7);
    const int lcol = (lt >> 1) << 4;

    const int CH = K >> 6;
    issue();

    for (int c = 0; c < CH; ++c){
        if (c + 1 < CH) { issue(); CP_WAIT(1); }
        else            { CP_WAIT(0); }
        __syncthreads();

        const uint32_t st = sbase + (uint32_t)((c & 1) * STAGE);
#pragma unroll
        for (int kk = 0; kk < 4; ++kk){
            const uint32_t kb = (uint32_t)(kk << 5);
            uint32_t ah[MT][4], al[MT][4];
#pragma unroll
            for (int mt = 0; mt < MT; ++mt){
                int r = warpM*32 + mt*16 + lrow;
                uint32_t cb = (kb + lcol) ^ ((uint32_t)(r&7) << 4);
                ldsm4(ah[mt], st + A_HI + r*128 + cb);
                ldsm4(al[mt], st + A_LO + r*128 + cb);
            }
#pragma unroll
            for (int g = 0; g < NG; ++g){
                uint32_t bh[4], bl[4];
                int r = warpN*WN + g*16 + lrow;
                uint32_t cb = (kb + lcol) ^ ((uint32_t)(r&7) << 4);
                ldsm4(bh, st + B_HI + r*128 + cb);
                ldsm4(bl, st + B_LO + r*128 + cb);
#pragma unroll
                for (int mt = 0; mt < MT; ++mt)
#pragma unroll
                    for (int sH = 0; sH < 2; ++sH)
                        mma16816(acc[mt][g*2+sH], ah[mt], bh[sH], bh[sH+2]);
#pragma unroll
                for (int mt = 0; mt < MT; ++mt)
#pragma unroll
                    for (int sH = 0; sH < 2; ++sH)
                        mma16816(acc[mt][g*2+sH], ah[mt], bl[sH], bl[sH+2]);
#pragma unroll
                for (int mt = 0; mt < MT; ++mt)
#pragma unroll
                    for (int sH = 0; sH < 2; ++sH)
                        mma16816(acc[mt][g*2+sH], al[mt], bh[sH], bh[sH+2]);
            }
        }
        __syncthreads();
    }

    // epilogue via padded smem
    float* sD = (float*)smem;
    constexpr int LDD = BN_ + 1;
#pragma unroll
    for (int mt = 0; mt < MT; ++mt)
#pragma unroll
        for (int nt = 0; nt < NTT; ++nt){
            int r0 = warpM*32 + mt*16 + (lane >> 2);
            int c0 = warpN*WN + nt*8 + (lane & 3)*2;
            sD[r0*LDD + c0]       = acc[mt][nt][0];
            sD[r0*LDD + c0 + 1]   = acc[mt][nt][1];
            sD[(r0+8)*LDD + c0]   = acc[mt][nt][2];
            sD[(r0+8)*LDD + c0+1] = acc[mt][nt][3];
        }
    __syncthreads();

    if (EPI == EPI_QKV3){
        const int which = nBase / HID;
        const int nloc0 = nBase - which*HID;
        const float* bs = (which==0) ? bias : (which==1) ? bias2 : bias3;
        bf* oHi = (which==0) ? outHi : (which==1) ? out2Hi : out3Hi;
        bf* oLo = (which==0) ? outLo : (which==1) ? out2Lo : out3Lo;
        if (which < 2){
            constexpr int NQ = BN_/4;
            for (int t = tid; t < BM_*NQ; t += NT){
                int m = t / NQ, nq = t % NQ;
                int nl = nloc0 + nq*4;
                int mg = mBase + m, b_ = mg >> 9, sidx = mg & 511;
                int h = nl >> 6, dd = nl & 63;
                float e[4];
#pragma unroll
                for (int j=0;j<4;j++) e[j] = sD[m*LDD + nq*4 + j] + bs[nl+j];
                bf h0,h1,h2,h3,l0,l1,l2,l3;
                bsplit(e[0],h0,l0); bsplit(e[1],h1,l1);
                bsplit(e[2],h2,l2); bsplit(e[3],h3,l3);
                long idx = ((long)(b_*NHEADS + h)*SEQ + sidx)*HDIM + dd;
                *(__nv_bfloat162*)&oHi[idx]   = __nv_bfloat162(h0,h1);
                *(__nv_bfloat162*)&oHi[idx+2] = __nv_bfloat162(h2,h3);
                *(__nv_bfloat162*)&oLo[idx]   = __nv_bfloat162(l0,l1);
                *(__nv_bfloat162*)&oLo[idx+2] = __nv_bfloat162(l2,l3);
            }
        } else {
            for (int t = tid; t < BM_*BN_; t += NT){
                int m = t & (BM_-1), n = t / BM_;
                int nl = nloc0 + n, h = nl >> 6, dd = nl & 63;
                int mg = mBase + m, b_ = mg >> 9, sidx = mg & 511;
                float v = sD[m*LDD + n] + bs[nl];
                bf hh, ll; bsplit(v, hh, ll);
                long idx = ((long)(b_*NHEADS + h)*HDIM + dd)*SEQ + sidx;
                oHi[idx] = hh; oLo[idx] = ll;
            }
        }
    } else {
        constexpr int NQ = BN_ / 4;
        for (int t = tid; t < BM_*NQ; t += NT){
            int m = t / NQ, nq = t % NQ;
            int n0 = nBase + nq*4;
            int mg = mBase + m;
            float e[4];
#pragma unroll
            for (int j=0;j<4;j++) e[j] = sD[m*LDD + nq*4 + j];
            if (EPI == EPI_PLAIN){
#pragma unroll
                for (int j=0;j<4;j++) e[j] += bias[n0+j];
                float4 v = {e[0],e[1],e[2],e[3]};
                *(float4*)&outF[(long)mg*ldc + n0] = v;
            } else { // EPI_GELU
#pragma unroll
                for (int j=0;j<4;j++){
                    float t2 = e[j] + bias[n0+j];
                    e[j] = 0.5f*t2*(1.f + erff(t2*0.70710678118654752f));
                }
                bf h0,h1,h2,h3,l0,l1,l2,l3;
                bsplit(e[0],h0,l0); bsplit(e[1],h1,l1);
                bsplit(e[2],h2,l2); bsplit(e[3],h3,l3);
                long idx = (long)mg*ldc + n0;
                *(__nv_bfloat162*)&outHi[idx]   = __nv_bfloat162(h0,h1);
                *(__nv_bfloat162*)&outHi[idx+2] = __nv_bfloat162(h2,h3);
                *(__nv_bfloat162*)&outLo[idx]   = __nv_bfloat162(l0,l1);
                *(__nv_bfloat162*)&outLo[idx+2] = __nv_bfloat162(l2,l3);
            }
        }
    }
}

// ---------------- host ----------------
#define SMEM_BIG  196608   // 2 stages * 96KB (128x256)
#define SMEM_SML  98304    // 2 stages * 48KB (64x128); 2 CTAs/SM

extern "C" void kernel_launch(void* const* d_in, const int* in_sizes, int n_in,
                              void* d_out, int out_size)
{
    const float* emb     = (const float*)d_in[0];
    const int*   seg     = (const int*)  d_in[1];
    const float* rel_emb = (const float*)d_in[2];
    const float* Wq = (const float*)d_in[3];  const float* bq = (const float*)d_in[4];
    const float* Wk = (const float*)d_in[5];  const float* bk = (const float*)d_in[6];
    const float* Wv = (const float*)d_in[7];  const float* bv = (const float*)d_in[8];
    const float* Wo = (const float*)d_in[9];  const float* bo = (const float*)d_in[10];
    const float* ln1_g = (const float*)d_in[11]; const float* ln1_b = (const float*)d_in[12];
    const float* W1 = (const float*)d_in[13]; const float* b1 = (const float*)d_in[14];
    const float* W2 = (const float*)d_in[15]; const float* b2 = (const float*)d_in[16];
    const float* ln2_g = (const float*)d_in[17]; const float* ln2_b = (const float*)d_in[18];
    float* out = (float*)d_out;

    static bool inited = false;
    static float *hid, *tmp, *pb, *mk;
    static bf *hA_h,*hA_l,*q_h,*q_l,*k_h,*k_l,*vt_h,*vt_l,*cx_h,*cx_l,*ff_h,*ff_l;
    static bf *wqkv_h,*wqkv_l,*wo_h,*wo_l,*w1_h,*w1_l,*w2_h,*w2_l;
    if (!inited){
        inited = true;
        cudaGetSymbolAddress((void**)&hid, g_hidden);
        cudaGetSymbolAddress((void**)&tmp, g_tmp);
        cudaGetSymbolAddress((void**)&pb,  g_pb);
        cudaGetSymbolAddress((void**)&mk,  g_mask);
        cudaGetSymbolAddress((void**)&hA_h, g_hidA_hi); cudaGetSymbolAddress((void**)&hA_l, g_hidA_lo);
        cudaGetSymbolAddress((void**)&q_h,  g_q_hi);    cudaGetSymbolAddress((void**)&q_l,  g_q_lo);
        cudaGetSymbolAddress((void**)&k_h,  g_k_hi);    cudaGetSymbolAddress((void**)&k_l,  g_k_lo);
        cudaGetSymbolAddress((void**)&vt_h, g_vt_hi);   cudaGetSymbolAddress((void**)&vt_l, g_vt_lo);
        cudaGetSymbolAddress((void**)&cx_h, g_ctx_hi);  cudaGetSymbolAddress((void**)&cx_l, g_ctx_lo);
        cudaGetSymbolAddress((void**)&ff_h, g_ff_hi);   cudaGetSymbolAddress((void**)&ff_l, g_ff_lo);
        cudaGetSymbolAddress((void**)&wqkv_h, g_WqkvT_hi); cudaGetSymbolAddress((void**)&wqkv_l, g_WqkvT_lo);
        cudaGetSymbolAddress((void**)&wo_h, g_WoT_hi);  cudaGetSymbolAddress((void**)&wo_l, g_WoT_lo);
        cudaGetSymbolAddress((void**)&w1_h, g_W1T_hi);  cudaGetSymbolAddress((void**)&w1_l, g_W1T_lo);
        cudaGetSymbolAddress((void**)&w2_h, g_W2T_hi);  cudaGetSymbolAddress((void**)&w2_l, g_W2T_lo);
        cudaFuncSetAttribute(mma_gemm<128,256,512,EPI_QKV3>, cudaFuncAttributeMaxDynamicSharedMemorySize, SMEM_BIG);
        cudaFuncSetAttribute(mma_gemm<128,256,512,EPI_GELU>, cudaFuncAttributeMaxDynamicSharedMemorySize, SMEM_BIG);
        cudaFuncSetAttribute(mma_gemm<64,128,256,EPI_PLAIN>, cudaFuncAttributeMaxDynamicSharedMemorySize, SMEM_SML);
        cudaFuncSetAttribute(flash_k, cudaFuncAttributeMaxDynamicSharedMemorySize, FLASH_SMEM);
    }

    // ---- setup: QKV GEMM stays at my launch index 3 ----
    tsplit_qkv_k<<<dim3(HID/32, HID/32, 3), dim3(32,8)>>>(Wq, Wk, Wv, wqkv_h, wqkv_l);     // 0
    split_copy_k<<<(ROWS*HID+255)/256, 256>>>(emb, hid, hA_h, hA_l, ROWS*HID);             // 1
    tsplit_k<<<dim3(HID/32, HID/32),   dim3(32,8)>>>(Wo, wo_h, wo_l, HID, HID);            // 2
    mma_gemm<128,256,512,EPI_QKV3><<<dim3(9,32,1),512,SMEM_BIG>>>(                          // 3
        hA_h,hA_l, wqkv_h,wqkv_l, HID, HID, HID,
        bq, bk, bv, nullptr, q_h,q_l, k_h,k_l, vt_h,vt_l, 0);
    mask_k<<<(ROWS+255)/256, 256>>>(seg, mk);
    posbias_k<<<(SEQ*SEQ+255)/256, 256>>>(rel_emb, pb);
    tsplit_k<<<dim3(FFDIM/32, HID/32), dim3(32,8)>>>(W1, w1_h, w1_l, HID, FFDIM);
    tsplit_k<<<dim3(HID/32, FFDIM/32), dim3(32,8)>>>(W2, w2_h, w2_l, FFDIM, HID);

    for (int L=0; L<NLAYERS; L++){
        if (L > 0)
            mma_gemm<128,256,512,EPI_QKV3><<<dim3(9,32,1),512,SMEM_BIG>>>(
                hA_h,hA_l, wqkv_h,wqkv_l, HID, HID, HID,
                bq, bk, bv, nullptr, q_h,q_l, k_h,k_l, vt_h,vt_l, 0);

        // fused attention
        flash_k<<<dim3(4, NBH), 512, FLASH_SMEM>>>(
            q_h,q_l, k_h,k_l, vt_h,vt_l, pb, mk, cx_h, cx_l);

        // O projection (64x128, 2 CTAs/SM)
        mma_gemm<64,128,256,EPI_PLAIN><<<dim3(6,64,1),256,SMEM_SML>>>(
            cx_h,cx_l, wo_h,wo_l, HID, HID, HID,
            bo,nullptr,nullptr, tmp, nullptr,nullptr, nullptr,nullptr, nullptr,nullptr, HID);
        resln_k<<<ROWS,256>>>(hid, tmp, ln1_g, ln1_b, hid, hA_h, hA_l);

        // FF1 (GELU), 128x256
        mma_gemm<128,256,512,EPI_GELU><<<dim3(12,32,1),512,SMEM_BIG>>>(
            hA_h,hA_l, w1_h,w1_l, HID, HID, HID,
            b1,nullptr,nullptr, nullptr, ff_h,ff_l, nullptr,nullptr, nullptr,nullptr, FFDIM);
        // FF2 (64x128, 2 CTAs/SM)
        mma_gemm<64,128,256,EPI_PLAIN><<<dim3(6,64,1),256,SMEM_SML>>>(
            ff_h,ff_l, w2_h,w2_l, FFDIM, FFDIM, FFDIM,
            b2,nullptr,nullptr, tmp, nullptr,nullptr, nullptr,nullptr, nullptr,nullptr, HID);
        resln_k<<<ROWS,256>>>(hid, tmp, ln2_g, ln2_b, (L==NLAYERS-1) ? out : hid, hA_h, hA_l);
    }
}